// round 1
// baseline (speedup 1.0000x reference)
#include <cuda_runtime.h>
#include <math.h>

// ---------------- scratch (device globals; no allocations) ----------------
#define NB 16
__device__ float g_h1[NB*64*256*256];   // 256 MB
__device__ float g_h2[NB*128*128*128];  // 128 MB
__device__ float g_h3[NB*256*64*64];    //  64 MB
__device__ float g_z [NB*512*32*32];    //  32 MB
__device__ float g_zf[NB*1024*512];     //  32 MB  (16384 x 512 row-major)
__device__ float g_zq[NB*512*32*32];    //  32 MB
__device__ float g_g1[NB*256*64*64];    //  64 MB
__device__ float g_g2[NB*128*128*128];  // 128 MB
__device__ float g_g3[NB*64*256*256];   // 256 MB
__device__ float g_cn[8192];
__device__ int   g_idx[16384];

// ---------------- direct 3x3 conv, pad=1 ----------------
// Thread: 4 horizontal outputs x TC output channels. Weights chunked in smem.
// ACT: 0 none, 1 relu, 2 sigmoid
template<int STRIDE, int TC, int ACT>
__global__ void __launch_bounds__(128) conv3x3_k(
    const float* __restrict__ in, const float* __restrict__ wgt,
    const float* __restrict__ bias, float* __restrict__ out,
    int Cin, int Cout, int Hin, int Win, int Hout, int Wout)
{
    constexpr int CICH = 32;
    constexpr int NC = (STRIDE == 1) ? 6 : 9;
    __shared__ float ws[CICH * TC * 9];

    const int tid  = threadIdx.x;
    const int W4   = Wout >> 2;          // 4-wide groups per row (8..64)
    const int rows = 128 / W4;
    const int lane = tid % W4;
    const int row  = tid / W4;
    const int oy   = blockIdx.y * rows + row;
    const int ox0  = lane * 4;
    const int ocg  = blockIdx.x * TC;
    const int n    = blockIdx.z;

    float acc[TC][4];
#pragma unroll
    for (int a = 0; a < TC; a++)
#pragma unroll
        for (int j = 0; j < 4; j++) acc[a][j] = 0.f;

    bool cval[NC];
#pragma unroll
    for (int c = 0; c < NC; c++) {
        int ix = ox0 * STRIDE + c - 1;
        cval[c] = (ix >= 0 && ix < Win);
    }
    const int ixbase = ox0 * STRIDE - 1;
    bool rval[3]; int iyo[3];
#pragma unroll
    for (int ky = 0; ky < 3; ky++) {
        int iy = oy * STRIDE + ky - 1;
        rval[ky] = (iy >= 0 && iy < Hin);
        iyo[ky] = iy;
    }

    for (int cc = 0; cc < Cin; cc += CICH) {
        const int chunk = min(CICH, Cin - cc);
        __syncthreads();
        for (int i = tid; i < chunk * TC * 9; i += 128) {
            int ci = i / (TC * 9);
            int r  = i - ci * (TC * 9);
            int oc = r / 9;
            int k  = r - oc * 9;
            ws[i] = wgt[(size_t)(ocg + oc) * Cin * 9 + (size_t)(cc + ci) * 9 + k];
        }
        __syncthreads();
        for (int ci = 0; ci < chunk; ci++) {
            const float* ip = in + ((size_t)n * Cin + cc + ci) * Hin * Win;
            float iv[3][NC];
#pragma unroll
            for (int ky = 0; ky < 3; ky++) {
                const float* rp = ip + (long)iyo[ky] * Win + ixbase;
#pragma unroll
                for (int c = 0; c < NC; c++)
                    iv[ky][c] = (rval[ky] && cval[c]) ? rp[c] : 0.f;
            }
            const float* wp = ws + ci * TC * 9;
#pragma unroll
            for (int oc = 0; oc < TC; oc++) {
#pragma unroll
                for (int ky = 0; ky < 3; ky++)
#pragma unroll
                    for (int kx = 0; kx < 3; kx++) {
                        float wv = wp[oc * 9 + ky * 3 + kx];
#pragma unroll
                        for (int j = 0; j < 4; j++)
                            acc[oc][j] = fmaf(iv[ky][j * STRIDE + kx], wv, acc[oc][j]);
                    }
            }
        }
    }
#pragma unroll
    for (int oc = 0; oc < TC; oc++) {
        float bv = bias[ocg + oc];
        float* op = out + (((size_t)n * Cout + ocg + oc) * Hout + oy) * Wout + ox0;
#pragma unroll
        for (int j = 0; j < 4; j++) {
            float v = acc[oc][j] + bv;
            if (ACT == 1) v = v > 0.f ? v : 0.f;
            if (ACT == 2) v = 1.f / (1.f + expf(-v));
            op[j] = v;
        }
    }
}

// ---------------- transposed conv k=3 s=2 p=1 op=1 (doubles H,W) ----------------
// out(oy,ox) += x(iy,ix) * w[ci][oc][ky][kx] with ky=oy-2iy+1, kx=ox-2ix+1.
// Thread computes the 2x4 output block (rows 2a,2a+1; cols 4q..4q+3) for TC ocs,
// needing only inputs x[a..a+1][2q..2q+2].
template<int TC, int ACT>
__global__ void __launch_bounds__(128) deconv_k(
    const float* __restrict__ in, const float* __restrict__ wgt,  // [Cin][Cout][3][3]
    const float* __restrict__ bias, float* __restrict__ out,
    int Cin, int Cout, int Hin, int Win)
{
    constexpr int CICH = 32;
    __shared__ float ws[CICH * TC * 9];
    const int Hout = Hin * 2, Wout = Win * 2;
    const int tid  = threadIdx.x;
    const int W4   = Wout >> 2;           // quad-pairs per output row
    const int rows = 128 / W4;            // input rows per block
    const int q    = tid % W4;
    const int a    = blockIdx.y * rows + tid / W4;  // input row
    const int b    = q * 2;                          // input col base
    const int ocg  = blockIdx.x * TC;
    const int n    = blockIdx.z;

    const bool v_a1 = (a + 1) < Hin;
    const bool v_b2 = (b + 2) < Win;

    float acc[TC][8];
#pragma unroll
    for (int o = 0; o < TC; o++)
#pragma unroll
        for (int j = 0; j < 8; j++) acc[o][j] = 0.f;

    for (int cc = 0; cc < Cin; cc += CICH) {
        const int chunk = min(CICH, Cin - cc);
        __syncthreads();
        for (int i = tid; i < chunk * TC * 9; i += 128) {
            int ci = i / (TC * 9);
            int r  = i - ci * (TC * 9);
            int oc = r / 9;
            int k  = r - oc * 9;
            ws[i] = wgt[(size_t)(cc + ci) * Cout * 9 + (size_t)(ocg + oc) * 9 + k];
        }
        __syncthreads();
        for (int ci = 0; ci < chunk; ci++) {
            const float* ip = in + ((size_t)n * Cin + cc + ci) * Hin * Win;
            const float* r0 = ip + (size_t)a * Win + b;
            float i00 = r0[0];
            float i01 = r0[1];
            float i02 = v_b2 ? r0[2] : 0.f;
            float i10 = 0.f, i11 = 0.f, i12 = 0.f;
            if (v_a1) {
                const float* r1 = r0 + Win;
                i10 = r1[0]; i11 = r1[1]; i12 = v_b2 ? r1[2] : 0.f;
            }
            const float* wp = ws + ci * TC * 9;
#pragma unroll
            for (int oc = 0; oc < TC; oc++) {
                float w00 = wp[oc*9+0], w01 = wp[oc*9+1], w02 = wp[oc*9+2];
                float w10 = wp[oc*9+3], w11 = wp[oc*9+4], w12 = wp[oc*9+5];
                float w20 = wp[oc*9+6], w21 = wp[oc*9+7], w22 = wp[oc*9+8];
                acc[oc][0] = fmaf(i00, w11, acc[oc][0]);
                acc[oc][1] = fmaf(i00, w12, fmaf(i01, w10, acc[oc][1]));
                acc[oc][2] = fmaf(i01, w11, acc[oc][2]);
                acc[oc][3] = fmaf(i01, w12, fmaf(i02, w10, acc[oc][3]));
                acc[oc][4] = fmaf(i00, w21, fmaf(i10, w01, acc[oc][4]));
                acc[oc][5] = fmaf(i00, w22, fmaf(i01, w20, fmaf(i10, w02, fmaf(i11, w00, acc[oc][5]))));
                acc[oc][6] = fmaf(i01, w21, fmaf(i11, w01, acc[oc][6]));
                acc[oc][7] = fmaf(i01, w22, fmaf(i02, w20, fmaf(i11, w02, fmaf(i12, w00, acc[oc][7]))));
            }
        }
    }
#pragma unroll
    for (int oc = 0; oc < TC; oc++) {
        float bv = bias[ocg + oc];
        float* op = out + (((size_t)n * Cout + ocg + oc) * Hout + 2 * a) * Wout + 4 * q;
#pragma unroll
        for (int j = 0; j < 4; j++) {
            float v = acc[oc][j] + bv;
            if (ACT == 1) v = v > 0.f ? v : 0.f;
            op[j] = v;
        }
        op += Wout;
#pragma unroll
        for (int j = 0; j < 4; j++) {
            float v = acc[oc][4 + j] + bv;
            if (ACT == 1) v = v > 0.f ? v : 0.f;
            op[j] = v;
        }
    }
}

// ---------------- z [B,512,32,32] -> zf [16384, 512] (channels-last rows) -------
__global__ void __launch_bounds__(256) zt_k(const float* __restrict__ z,
                                            float* __restrict__ zf)
{
    __shared__ float t[128 * 33];
    const int blk = blockIdx.x;        // b*32 + y
    const int bb  = blk >> 5;
    const int y   = blk & 31;
    const int tid = threadIdx.x;
    for (int cc = 0; cc < 512; cc += 128) {
        __syncthreads();
        for (int i = tid; i < 128 * 32; i += 256) {
            int c = i >> 5, x = i & 31;
            t[c * 33 + x] = z[(((size_t)bb * 512 + cc + c) * 32 + y) * 32 + x];
        }
        __syncthreads();
        for (int i = tid; i < 32 * 128; i += 256) {
            int x = i >> 7, c = i & 127;
            zf[((size_t)bb * 1024 + y * 32 + x) * 512 + cc + c] = t[c * 33 + x];
        }
    }
}

// ---------------- codebook row norms ----------------
__global__ void __launch_bounds__(256) cnorm_k(const float* __restrict__ cb,
                                               float* __restrict__ cn)
{
    const int warp = threadIdx.x >> 5, lane = threadIdx.x & 31;
    const int code = blockIdx.x * 8 + warp;
    const float* p = cb + (size_t)code * 512;
    float s = 0.f;
    for (int d = lane; d < 512; d += 32) { float v = p[d]; s = fmaf(v, v, s); }
#pragma unroll
    for (int o = 16; o > 0; o >>= 1) s += __shfl_xor_sync(0xffffffffu, s, o);
    if (lane == 0) cn[code] = s;
}

// ---------------- quantizer: argmin over 8192 codes for 16 rows per block -------
__global__ void __launch_bounds__(256) quant_k(const float* __restrict__ zf,
                                               const float* __restrict__ cb,
                                               const float* __restrict__ cn,
                                               int* __restrict__ idx)
{
    extern __shared__ float sm[];
    float* zs  = sm;               // 16*512
    float* cbs = sm + 16 * 512;    // 512*33 (padded)
    const int tid = threadIdx.x;
    const int r0  = blockIdx.x * 16;

    for (int i = tid; i < 16 * 512; i += 256) zs[i] = zf[(size_t)r0 * 512 + i];

    float best[16]; int bi[16];
#pragma unroll
    for (int r = 0; r < 16; r++) { best[r] = 3.4e38f; bi[r] = 0; }

    for (int ct = 0; ct < 16; ct++) {
        const int cbase = ct * 512;
        float dot0[16], dot1[16];
#pragma unroll
        for (int r = 0; r < 16; r++) { dot0[r] = 0.f; dot1[r] = 0.f; }
        for (int dt = 0; dt < 16; dt++) {
            __syncthreads();
            for (int i = tid; i < 512 * 32; i += 256) {
                int c = i >> 5, d = i & 31;
                cbs[c * 33 + d] = cb[(size_t)(cbase + c) * 512 + dt * 32 + d];
            }
            __syncthreads();
#pragma unroll 4
            for (int d = 0; d < 32; d++) {
                float c0 = cbs[tid * 33 + d];
                float c1 = cbs[(tid + 256) * 33 + d];
                const float* zp = zs + dt * 32 + d;
#pragma unroll
                for (int r = 0; r < 16; r++) {
                    float zv = zp[r * 512];
                    dot0[r] = fmaf(zv, c0, dot0[r]);
                    dot1[r] = fmaf(zv, c1, dot1[r]);
                }
            }
        }
        float n0 = cn[cbase + tid], n1 = cn[cbase + 256 + tid];
#pragma unroll
        for (int r = 0; r < 16; r++) {
            float s0 = n0 - 2.f * dot0[r];
            float s1 = n1 - 2.f * dot1[r];
            if (s0 < best[r]) { best[r] = s0; bi[r] = cbase + tid; }
            if (s1 < best[r]) { best[r] = s1; bi[r] = cbase + 256 + tid; }
        }
    }
    // block-wide argmin per row (lowest index on ties, matching argmin)
    float* sv = sm;
    int*   si = (int*)(sm + 256);
    for (int r = 0; r < 16; r++) {
        __syncthreads();
        sv[tid] = best[r]; si[tid] = bi[r];
        __syncthreads();
        for (int s = 128; s > 0; s >>= 1) {
            if (tid < s) {
                float ov = sv[tid + s]; int oi = si[tid + s];
                if (ov < sv[tid] || (ov == sv[tid] && oi < si[tid])) { sv[tid] = ov; si[tid] = oi; }
            }
            __syncthreads();
        }
        if (tid == 0) idx[r0 + r] = si[0];
    }
}

// ---------------- zq gather: zq[b][c][y][x] = cb[idx[n]][c] ----------------
__global__ void __launch_bounds__(256) zqg_k(const float* __restrict__ cb,
                                             const int* __restrict__ idx,
                                             float* __restrict__ zq)
{
    size_t i = (size_t)blockIdx.x * 256 + threadIdx.x;
    if (i >= (size_t)NB * 512 * 32 * 32) return;
    int x = (int)(i & 31);
    int y = (int)((i >> 5) & 31);
    int c = (int)((i >> 10) & 511);
    int bb = (int)(i >> 19);
    int n = bb * 1024 + y * 32 + x;
    zq[i] = cb[(size_t)idx[n] * 512 + c];
}

// ---------------- indices -> tail of output (as float) ----------------
__global__ void __launch_bounds__(256) idxout_k(const int* __restrict__ idx,
                                                float* __restrict__ out,
                                                long out_off, long out_size)
{
    int i = blockIdx.x * 256 + threadIdx.x;
    if (i < 16384 && out_off + i < out_size) out[out_off + i] = (float)idx[i];
}

// ---------------- host launcher ----------------
extern "C" void kernel_launch(void* const* d_in, const int* in_sizes, int n_in,
                              void* d_out, int out_size)
{
    const float* x  = (const float*)d_in[0];
    const float* w1 = (const float*)d_in[1];  const float* b1 = (const float*)d_in[2];
    const float* w2 = (const float*)d_in[3];  const float* b2 = (const float*)d_in[4];
    const float* w3 = (const float*)d_in[5];  const float* b3 = (const float*)d_in[6];
    const float* w4 = (const float*)d_in[7];  const float* b4 = (const float*)d_in[8];
    const float* cb = (const float*)d_in[9];
    const float* d1w = (const float*)d_in[10]; const float* d1b = (const float*)d_in[11];
    const float* d2w = (const float*)d_in[12]; const float* d2b = (const float*)d_in[13];
    const float* d3w = (const float*)d_in[14]; const float* d3b = (const float*)d_in[15];
    const float* wo = (const float*)d_in[16]; const float* bo = (const float*)d_in[17];
    float* out = (float*)d_out;

    float *h1, *h2, *h3, *z, *zf, *zq, *g1, *g2, *g3, *cn;
    int* idx;
    cudaGetSymbolAddress((void**)&h1, g_h1);
    cudaGetSymbolAddress((void**)&h2, g_h2);
    cudaGetSymbolAddress((void**)&h3, g_h3);
    cudaGetSymbolAddress((void**)&z,  g_z);
    cudaGetSymbolAddress((void**)&zf, g_zf);
    cudaGetSymbolAddress((void**)&zq, g_zq);
    cudaGetSymbolAddress((void**)&g1, g_g1);
    cudaGetSymbolAddress((void**)&g2, g_g2);
    cudaGetSymbolAddress((void**)&g3, g_g3);
    cudaGetSymbolAddress((void**)&cn, g_cn);
    cudaGetSymbolAddress((void**)&idx, g_idx);

    // Encoder
    conv3x3_k<1, 8, 1><<<dim3(8, 128, NB), 128>>>(x,  w1, b1, h1,   3,  64, 256, 256, 256, 256);
    conv3x3_k<2, 8, 1><<<dim3(16, 32, NB), 128>>>(h1, w2, b2, h2,  64, 128, 256, 256, 128, 128);
    conv3x3_k<2, 8, 1><<<dim3(32,  8, NB), 128>>>(h2, w3, b3, h3, 128, 256, 128, 128,  64,  64);
    conv3x3_k<2, 8, 0><<<dim3(64,  2, NB), 128>>>(h3, w4, b4, z,  256, 512,  64,  64,  32,  32);

    // Quantize
    zt_k<<<512, 256>>>(z, zf);
    cnorm_k<<<1024, 256>>>(cb, cn);
    cudaFuncSetAttribute(quant_k, cudaFuncAttributeMaxDynamicSharedMemorySize, 100352);
    quant_k<<<1024, 256, 100352>>>(zf, cb, cn, idx);
    zqg_k<<<(NB * 512 * 32 * 32 + 255) / 256, 256>>>(cb, idx, zq);

    // Decoder
    deconv_k<8, 1><<<dim3(32,  4, NB), 128>>>(zq, d1w, d1b, g1, 512, 256,  32,  32);
    deconv_k<8, 1><<<dim3(16, 16, NB), 128>>>(g1, d2w, d2b, g2, 256, 128,  64,  64);
    deconv_k<8, 1><<<dim3( 8, 64, NB), 128>>>(g2, d3w, d3b, g3, 128,  64, 128, 128);
    conv3x3_k<1, 3, 2><<<dim3(1, 128, NB), 128>>>(g3, wo, bo, out, 64, 3, 256, 256, 256, 256);

    // Indices appended after reconstruction (concat output convention)
    idxout_k<<<64, 256>>>(idx, out, (long)NB * 3 * 256 * 256, (long)out_size);
}